// round 8
// baseline (speedup 1.0000x reference)
#include <cuda_runtime.h>
#include <cuda_fp16.h>
#include <cstdint>

#define NUM_LAYERS 16
#define KS 31
#define HH 1024
#define WW 1024
#define IMW 1054          // 1024 + 31 - 1
#define NC 3
#define TAPS (KS * KS)    // 961
#define TDIM 256
#define XT 16             // x-tiles of 8 px -> 128 px per block
#define SROW 160          // smem pair-row stride (u32), indices 0..158 used
#define WROWS 46          // 2 tiles x 8 rows + 30 halo

// weights pre-packed as per-lane m16n8k16 f16 A-fragments:
// [c][ky][slice(2)][lane] -> uint4 {a0,a1,a2,a3} (each a f16x2)
__device__ uint4 g_wfrag[NC * KS * 2 * 32];

__device__ __forceinline__ void mma16(float* d, uint32_t a0, uint32_t a1,
                                      uint32_t a2, uint32_t a3,
                                      uint32_t b0, uint32_t b1) {
    asm volatile(
        "mma.sync.aligned.m16n8k16.row.col.f32.f16.f16.f32 "
        "{%0,%1,%2,%3}, {%4,%5,%6,%7}, {%8,%9}, {%0,%1,%2,%3};"
        : "+f"(d[0]), "+f"(d[1]), "+f"(d[2]), "+f"(d[3])
        : "r"(a0), "r"(a1), "r"(a2), "r"(a3), "r"(b0), "r"(b1));
}

__device__ __forceinline__ uint32_t pack_h2(float lo, float hi) {
    __half2 h = __halves2half2(__float2half_rn(lo), __float2half_rn(hi));
    return *(uint32_t*)&h;
}

// Pack weights into m16n8k16 f16 A-fragment order (M=16 layers, K=16 taps/slice).
__global__ void prep_w(const float* __restrict__ w) {
    int i = blockIdx.x * blockDim.x + threadIdx.x;
    if (i >= NC * KS * 2 * 32) return;
    int lane = i & 31;
    int s    = (i >> 5) & 1;
    int ky   = (i >> 6) % KS;
    int c    = i / (KS * 2 * 32);
    int g = lane >> 2, t = lane & 3;
    const float* wc = w + (size_t)c * NUM_LAYERS * TAPS + (size_t)ky * KS;
    auto W = [&](int l, int k) -> float {
        int kx = 16 * s + k;
        return (kx < KS) ? wc[(size_t)l * TAPS + kx] : 0.0f;
    };
    uint4 v;
    v.x = pack_h2(W(g,     2 * t),     W(g,     2 * t + 1));
    v.y = pack_h2(W(g + 8, 2 * t),     W(g + 8, 2 * t + 1));
    v.z = pack_h2(W(g,     2 * t + 8), W(g,     2 * t + 9));
    v.w = pack_h2(W(g + 8, 2 * t + 8), W(g + 8, 2 * t + 9));
    g_wfrag[i] = v;
}

__global__ void __launch_bounds__(TDIM, 2)
blur_mma(const float* __restrict__ img, const int* __restrict__ idxp,
         const float* __restrict__ alpha, float* __restrict__ out)
{
    __shared__ uint32_t pairs[WROWS * SROW];  // 46-row sliding window of f16x2 pairs
    __shared__ float    dsm[8][16][33];       // per-warp D transpose buffer

    const int c  = blockIdx.z;
    const int x0 = blockIdx.x * 128;
    const int y0 = blockIdx.y * 16;           // 2 tiles: y0, y0+8
    const int tid = threadIdx.x, wid = tid >> 5, lane = tid & 31;
    const int g = lane >> 2, t = lane & 3;

    const float* ims = img + (size_t)c * IMW * IMW + (size_t)y0 * IMW + x0;
    const int rem  = IMW - x0;
    const int minr = rem < 159 ? rem : 159;   // valid pair cols

    // ---- initial staging: rows 0..37 (relative) ----
    for (int i = tid; i < 38 * SROW; i += TDIM) {
        int r = i / SROW, cc = i - r * SROW;
        float a = (cc     < minr) ? __ldg(ims + (size_t)r * IMW + cc)     : 0.0f;
        float b = (cc + 1 < minr) ? __ldg(ims + (size_t)r * IMW + cc + 1) : 0.0f;
        pairs[i] = pack_h2(a, b);
    }
    __syncthreads();

    const uint4* wf = g_wfrag + (size_t)c * KS * 2 * 32 + lane;
    const int idx = *idxp;

    #pragma unroll
    for (int tt = 0; tt < 2; ++tt) {
        float acc[XT][4];
        #pragma unroll
        for (int xt = 0; xt < XT; ++xt)
            acc[xt][0] = acc[xt][1] = acc[xt][2] = acc[xt][3] = 0.0f;

        for (int ky = 0; ky < KS; ++ky) {
            // interleaved staging of rows 38..45 during tile 0's compute:
            // 1280 words = exactly one word per thread at ky 0..4
            if (tt == 0 && ky < 5) {
                int w2 = ky * TDIM + tid;
                int r = 38 + w2 / SROW, cc = w2 - (w2 / SROW) * SROW;
                float a = (cc     < minr) ? __ldg(ims + (size_t)r * IMW + cc)     : 0.0f;
                float b = (cc + 1 < minr) ? __ldg(ims + (size_t)r * IMW + cc + 1) : 0.0f;
                pairs[r * SROW + cc] = pack_h2(a, b);
            }

            uint4 A0 = wf[(ky * 2 + 0) * 32];
            uint4 A1 = wf[(ky * 2 + 1) * 32];

            const uint32_t* rp = pairs + (tt * 8 + wid + ky) * SROW + g + 2 * t;
            uint32_t B0[4];
            #pragma unroll
            for (int j = 0; j < 4; ++j) B0[j] = rp[8 * j];

            #pragma unroll
            for (int xt = 0; xt < XT; ++xt) {
                mma16(acc[xt], A0.x, A0.y, A0.z, A0.w,
                      B0[xt & 3], B0[(xt + 1) & 3]);
                mma16(acc[xt], A1.x, A1.y, A1.z, A1.w,
                      B0[(xt + 2) & 3], B0[(xt + 3) & 3]);
                if (xt < XT - 1)               // slot xt&3 -> B0(xt+4)
                    B0[xt & 3] = rp[8 * (xt + 4)];
            }
        }
        __syncthreads();   // tile-1 rows fully staged; tile-t reads done

        // ---- epilogue: out[c,y,x] = sum_l D[l,x] * alpha[idx,l,y,x] ----
        const int y = y0 + tt * 8 + wid;
        #pragma unroll
        for (int ch = 0; ch < 4; ++ch) {       // 4 chunks of 32 px
            #pragma unroll
            for (int q = 0; q < 4; ++q) {
                int xt = ch * 4 + q;
                int xl = q * 8 + 2 * t;
                dsm[wid][g][xl]         = acc[xt][0];
                dsm[wid][g][xl + 1]     = acc[xt][1];
                dsm[wid][g + 8][xl]     = acc[xt][2];
                dsm[wid][g + 8][xl + 1] = acc[xt][3];
            }
            __syncwarp();
            const int xo = x0 + ch * 32 + lane;
            const float* ap = alpha + (((size_t)idx * NUM_LAYERS) * HH + y) * WW + xo;
            float s = 0.0f;
            #pragma unroll
            for (int l = 0; l < NUM_LAYERS; ++l)
                s += dsm[wid][l][lane] * __ldg(ap + (size_t)l * (HH * WW));
            out[((size_t)c * HH + y) * WW + xo] = s;
            __syncwarp();
        }
    }
}

extern "C" void kernel_launch(void* const* d_in, const int* in_sizes, int n_in,
                              void* d_out, int out_size) {
    const float* img   = (const float*)d_in[0];
    const int*   idxp  = (const int*)d_in[1];
    const float* w     = (const float*)d_in[2];
    const float* alpha = (const float*)d_in[3];
    float*       out   = (float*)d_out;

    prep_w<<<(NC * KS * 2 * 32 + 255) / 256, 256>>>(w);

    dim3 grid(WW / 128, HH / 16, NC);
    blur_mma<<<grid, TDIM>>>(img, idxp, alpha, out);
}

// round 9
// speedup vs baseline: 1.0745x; 1.0745x over previous
#include <cuda_runtime.h>
#include <cuda_fp16.h>
#include <cstdint>

#define NUM_LAYERS 16
#define KS 31
#define HH 1024
#define WW 1024
#define IMW 1054          // 1024 + 31 - 1
#define NC 3
#define TAPS (KS * KS)    // 961
#define TDIM 256
#define XT 16             // x-tiles of 8 px -> 128 px per block
#define SROW 160          // smem pair-row stride (u32), indices 0..157 used
#define NROWS 38          // 8 y-rows + 30 halo

// weights pre-packed as per-lane m16n8k16 f16 A-fragments:
// [c][ky][slice(2)][lane] -> uint4 {a0,a1,a2,a3} (each a f16x2)
__device__ uint4 g_wfrag[NC * KS * 2 * 32];

__device__ __forceinline__ void mma16(float* d, uint32_t a0, uint32_t a1,
                                      uint32_t a2, uint32_t a3,
                                      uint32_t b0, uint32_t b1) {
    asm volatile(
        "mma.sync.aligned.m16n8k16.row.col.f32.f16.f16.f32 "
        "{%0,%1,%2,%3}, {%4,%5,%6,%7}, {%8,%9}, {%0,%1,%2,%3};"
        : "+f"(d[0]), "+f"(d[1]), "+f"(d[2]), "+f"(d[3])
        : "r"(a0), "r"(a1), "r"(a2), "r"(a3), "r"(b0), "r"(b1));
}

__device__ __forceinline__ uint32_t pack_h2(float lo, float hi) {
    __half2 h = __halves2half2(__float2half_rn(lo), __float2half_rn(hi));
    return *(uint32_t*)&h;
}

// Pack weights into m16n8k16 f16 A-fragment order (M=16 layers, K=16 taps/slice).
__global__ void prep_w(const float* __restrict__ w) {
    int i = blockIdx.x * blockDim.x + threadIdx.x;
    if (i >= NC * KS * 2 * 32) return;
    int lane = i & 31;
    int s    = (i >> 5) & 1;
    int ky   = (i >> 6) % KS;
    int c    = i / (KS * 2 * 32);
    int g = lane >> 2, t = lane & 3;
    const float* wc = w + (size_t)c * NUM_LAYERS * TAPS + (size_t)ky * KS;
    auto W = [&](int l, int k) -> float {
        int kx = 16 * s + k;
        return (kx < KS) ? wc[(size_t)l * TAPS + kx] : 0.0f;
    };
    uint4 v;
    v.x = pack_h2(W(g,     2 * t),     W(g,     2 * t + 1));
    v.y = pack_h2(W(g + 8, 2 * t),     W(g + 8, 2 * t + 1));
    v.z = pack_h2(W(g,     2 * t + 8), W(g,     2 * t + 9));
    v.w = pack_h2(W(g + 8, 2 * t + 8), W(g + 8, 2 * t + 9));
    g_wfrag[i] = v;
}

__global__ void __launch_bounds__(TDIM, 2)
blur_mma(const float* __restrict__ img, const int* __restrict__ idxp,
         const float* __restrict__ alpha, float* __restrict__ out)
{
    __shared__ uint32_t pairs[NROWS * SROW];  // overlapping f16x2 pairs {v[i], v[i+1]}
    __shared__ float    dsm[8][16][33];       // per-warp D transpose buffer

    const int c  = blockIdx.z;
    const int x0 = blockIdx.x * 128;
    const int y0 = blockIdx.y * 8;
    const int tid = threadIdx.x, wid = tid >> 5, lane = tid & 31;
    const int g = lane >> 2, t = lane & 3;

    // stage image patch as overlapping half2 pairs (38 rows x 159 pair-words)
    const float* ims = img + (size_t)c * IMW * IMW + (size_t)y0 * IMW + x0;
    for (int i = tid; i < NROWS * SROW; i += TDIM) {
        int r = i / SROW, cc = i - r * SROW;
        float a = (cc < 159 && x0 + cc     < IMW) ? __ldg(ims + (size_t)r * IMW + cc)     : 0.0f;
        float b = (cc < 158 && x0 + cc + 1 < IMW) ? __ldg(ims + (size_t)r * IMW + cc + 1) : 0.0f;
        pairs[i] = pack_h2(a, b);
    }
    __syncthreads();

    float acc[XT][4];
    #pragma unroll
    for (int xt = 0; xt < XT; ++xt)
        acc[xt][0] = acc[xt][1] = acc[xt][2] = acc[xt][3] = 0.0f;

    const uint4* wf = g_wfrag + (size_t)c * KS * 2 * 32 + lane;

    for (int ky = 0; ky < KS; ++ky) {
        // A fragments (weights) for the 2 k16-slices of this ky
        uint4 A0 = wf[(ky * 2 + 0) * 32];
        uint4 A1 = wf[(ky * 2 + 1) * 32];

        // B ring (8-deep): B0(j) = pairs[row][8j + g + 2t]; frag F(j) = {B0(j), B0(j+1)}
        const uint32_t* rp = pairs + (wid + ky) * SROW + g + 2 * t;
        uint32_t B0[8];
        #pragma unroll
        for (int j = 0; j < 8; ++j) B0[j] = rp[8 * j];

        #pragma unroll
        for (int xt = 0; xt < XT; ++xt) {
            // slice 0: F(xt) = {B0(xt), B0(xt+1)}, slice 1: F(xt+2)
            mma16(acc[xt], A0.x, A0.y, A0.z, A0.w,
                  B0[xt & 7], B0[(xt + 1) & 7]);
            mma16(acc[xt], A1.x, A1.y, A1.z, A1.w,
                  B0[(xt + 2) & 7], B0[(xt + 3) & 7]);
            if (xt <= 10)                    // slot xt&7 -> B0(xt+8), used at xt+5
                B0[xt & 7] = rp[8 * (xt + 8)];
        }
    }

    // ---- epilogue: out[c,y,x] = sum_l D[l,x] * alpha[idx,l,y,x] ----
    const int idx = *idxp;
    const int y = y0 + wid;
    #pragma unroll
    for (int ch = 0; ch < 4; ++ch) {          // 4 chunks of 32 px
        #pragma unroll
        for (int q = 0; q < 4; ++q) {
            int xt = ch * 4 + q;
            int xl = q * 8 + 2 * t;
            dsm[wid][g][xl]         = acc[xt][0];
            dsm[wid][g][xl + 1]     = acc[xt][1];
            dsm[wid][g + 8][xl]     = acc[xt][2];
            dsm[wid][g + 8][xl + 1] = acc[xt][3];
        }
        __syncwarp();
        const int xo = x0 + ch * 32 + lane;
        const float* ap = alpha + (((size_t)idx * NUM_LAYERS) * HH + y) * WW + xo;
        float s = 0.0f;
        #pragma unroll
        for (int l = 0; l < NUM_LAYERS; ++l)
            s += dsm[wid][l][lane] * __ldg(ap + (size_t)l * (HH * WW));
        out[((size_t)c * HH + y) * WW + xo] = s;
        __syncwarp();
    }
}

extern "C" void kernel_launch(void* const* d_in, const int* in_sizes, int n_in,
                              void* d_out, int out_size) {
    const float* img   = (const float*)d_in[0];
    const int*   idxp  = (const int*)d_in[1];
    const float* w     = (const float*)d_in[2];
    const float* alpha = (const float*)d_in[3];
    float*       out   = (float*)d_out;

    prep_w<<<(NC * KS * 2 * 32 + 255) / 256, 256>>>(w);

    dim3 grid(WW / 128, HH / 8, NC);
    blur_mma<<<grid, TDIM>>>(img, idxp, alpha, out);
}

// round 10
// speedup vs baseline: 1.0849x; 1.0096x over previous
#include <cuda_runtime.h>
#include <cuda_fp16.h>
#include <cstdint>

#define NUM_LAYERS 16
#define KS 31
#define HH 1024
#define WW 1024
#define IMW 1054          // 1024 + 31 - 1
#define NC 3
#define TAPS (KS * KS)    // 961
#define TDIM 256
#define XT 16             // x-tiles of 8 px -> 128 px per block
#define SROW 160          // smem pair-row stride (u32), indices 0..158 used
#define NROWS 38          // 8 y-rows + 30 halo

// dynamic smem layout (bytes)
#define PAIRS_WORDS (NROWS * SROW)            // 6080 u32 = 24320 B
#define WF_OFF  (PAIRS_WORDS * 4)             // 24320
#define WF_ELEMS (KS * 2 * 32)                // 1984 uint4 = 31744 B
#define DSM_OFF (WF_OFF + WF_ELEMS * 16)      // 56064
#define SMEM_BYTES (DSM_OFF + 8 * 16 * 33 * 4)  // 72960

// weights pre-packed as per-lane m16n8k16 f16 A-fragments:
// [c][ky][slice(2)][lane] -> uint4 {a0,a1,a2,a3} (each a f16x2)
__device__ uint4 g_wfrag[NC * KS * 2 * 32];

__device__ __forceinline__ void mma16(float* d, uint32_t a0, uint32_t a1,
                                      uint32_t a2, uint32_t a3,
                                      uint32_t b0, uint32_t b1) {
    asm volatile(
        "mma.sync.aligned.m16n8k16.row.col.f32.f16.f16.f32 "
        "{%0,%1,%2,%3}, {%4,%5,%6,%7}, {%8,%9}, {%0,%1,%2,%3};"
        : "+f"(d[0]), "+f"(d[1]), "+f"(d[2]), "+f"(d[3])
        : "r"(a0), "r"(a1), "r"(a2), "r"(a3), "r"(b0), "r"(b1));
}

__device__ __forceinline__ uint32_t pack_h2(float lo, float hi) {
    __half2 h = __halves2half2(__float2half_rn(lo), __float2half_rn(hi));
    return *(uint32_t*)&h;
}

// Pack weights into m16n8k16 f16 A-fragment order (M=16 layers, K=16 taps/slice).
__global__ void prep_w(const float* __restrict__ w) {
    int i = blockIdx.x * blockDim.x + threadIdx.x;
    if (i >= NC * KS * 2 * 32) return;
    int lane = i & 31;
    int s    = (i >> 5) & 1;
    int ky   = (i >> 6) % KS;
    int c    = i / (KS * 2 * 32);
    int g = lane >> 2, t = lane & 3;
    const float* wc = w + (size_t)c * NUM_LAYERS * TAPS + (size_t)ky * KS;
    auto W = [&](int l, int k) -> float {
        int kx = 16 * s + k;
        return (kx < KS) ? wc[(size_t)l * TAPS + kx] : 0.0f;
    };
    uint4 v;
    v.x = pack_h2(W(g,     2 * t),     W(g,     2 * t + 1));
    v.y = pack_h2(W(g + 8, 2 * t),     W(g + 8, 2 * t + 1));
    v.z = pack_h2(W(g,     2 * t + 8), W(g,     2 * t + 9));
    v.w = pack_h2(W(g + 8, 2 * t + 8), W(g + 8, 2 * t + 9));
    g_wfrag[i] = v;
}

__global__ void __launch_bounds__(TDIM, 2)
blur_mma(const float* __restrict__ img, const int* __restrict__ idxp,
         const float* __restrict__ alpha, float* __restrict__ out)
{
    extern __shared__ char smem[];
    uint32_t* pairs = (uint32_t*)smem;                    // f16x2 pair table
    uint4*    wfs   = (uint4*)(smem + WF_OFF);            // A-fragments in smem
    float*    dsm   = (float*)(smem + DSM_OFF);           // [8][16][33] transpose buf

    const int c  = blockIdx.z;
    const int x0 = blockIdx.x * 128;
    const int y0 = blockIdx.y * 8;
    const int tid = threadIdx.x, wid = tid >> 5, lane = tid & 31;
    const int g = lane >> 2, t = lane & 3;

    // stage A-fragments for this channel into smem (L2-hot, 8x LDG.128/thread)
    const uint4* wfg = g_wfrag + (size_t)c * WF_ELEMS;
    for (int i = tid; i < WF_ELEMS; i += TDIM) wfs[i] = wfg[i];

    // stage image patch as overlapping half2 pairs (38 rows x 159 pair-words)
    const float* ims = img + (size_t)c * IMW * IMW + (size_t)y0 * IMW + x0;
    for (int i = tid; i < NROWS * SROW; i += TDIM) {
        int r = i / SROW, cc = i - r * SROW;
        float a = (cc < 159 && x0 + cc     < IMW) ? __ldg(ims + (size_t)r * IMW + cc)     : 0.0f;
        float b = (cc < 158 && x0 + cc + 1 < IMW) ? __ldg(ims + (size_t)r * IMW + cc + 1) : 0.0f;
        pairs[i] = pack_h2(a, b);
    }
    __syncthreads();

    float acc[XT][4];
    #pragma unroll
    for (int xt = 0; xt < XT; ++xt)
        acc[xt][0] = acc[xt][1] = acc[xt][2] = acc[xt][3] = 0.0f;

    // per-warp ky rotation: decorrelate loop-head stalls across SMSP warps
    const int kyw = (wid * 4) % KS;

    for (int kk = 0; kk < KS; ++kk) {
        int ky = kyw + kk; if (ky >= KS) ky -= KS;

        // A fragments from smem (29-cyc LDS.128, conflict-free)
        uint4 A0 = wfs[(ky * 2 + 0) * 32 + lane];
        uint4 A1 = wfs[(ky * 2 + 1) * 32 + lane];

        // B ring: B0(j) = pairs[row][8j + g + 2t]; frag F(j) = {B0(j), B0(j+1)}
        const uint32_t* rp = pairs + (wid + ky) * SROW + g + 2 * t;
        uint32_t B0[4];
        #pragma unroll
        for (int j = 0; j < 4; ++j) B0[j] = rp[8 * j];

        #pragma unroll
        for (int xt = 0; xt < XT; ++xt) {
            // slice 0: F(xt), slice 1: F(xt+2)
            mma16(acc[xt], A0.x, A0.y, A0.z, A0.w,
                  B0[xt & 3], B0[(xt + 1) & 3]);
            mma16(acc[xt], A1.x, A1.y, A1.z, A1.w,
                  B0[(xt + 2) & 3], B0[(xt + 3) & 3]);
            if (xt < XT - 1)                   // slot xt&3 -> B0(xt+4)
                B0[xt & 3] = rp[8 * (xt + 4)];
        }
    }

    // ---- epilogue: out[c,y,x] = sum_l D[l,x] * alpha[idx,l,y,x] ----
    const int idx = *idxp;
    const int y = y0 + wid;
    float* dw = dsm + wid * (16 * 33);
    #pragma unroll
    for (int ch = 0; ch < 4; ++ch) {          // 4 chunks of 32 px
        #pragma unroll
        for (int q = 0; q < 4; ++q) {
            int xt = ch * 4 + q;
            int xl = q * 8 + 2 * t;
            dw[g * 33 + xl]           = acc[xt][0];
            dw[g * 33 + xl + 1]       = acc[xt][1];
            dw[(g + 8) * 33 + xl]     = acc[xt][2];
            dw[(g + 8) * 33 + xl + 1] = acc[xt][3];
        }
        __syncwarp();
        const int xo = x0 + ch * 32 + lane;
        const float* ap = alpha + (((size_t)idx * NUM_LAYERS) * HH + y) * WW + xo;
        float s = 0.0f;
        #pragma unroll
        for (int l = 0; l < NUM_LAYERS; ++l)
            s += dw[l * 33 + lane] * __ldg(ap + (size_t)l * (HH * WW));
        out[((size_t)c * HH + y) * WW + xo] = s;
        __syncwarp();
    }
}

extern "C" void kernel_launch(void* const* d_in, const int* in_sizes, int n_in,
                              void* d_out, int out_size) {
    const float* img   = (const float*)d_in[0];
    const int*   idxp  = (const int*)d_in[1];
    const float* w     = (const float*)d_in[2];
    const float* alpha = (const float*)d_in[3];
    float*       out   = (float*)d_out;

    prep_w<<<(NC * KS * 2 * 32 + 255) / 256, 256>>>(w);

    cudaFuncSetAttribute(blur_mma,
                         cudaFuncAttributeMaxDynamicSharedMemorySize, SMEM_BYTES);
    dim3 grid(WW / 128, HH / 8, NC);
    blur_mma<<<grid, TDIM, SMEM_BYTES>>>(img, idxp, alpha, out);
}